// round 1
// baseline (speedup 1.0000x reference)
#include <cuda_runtime.h>
#include <math.h>
#include <float.h>

#define BB 8
#define NQ 4096
#define QD 1280
#define CD 1024
#define CTX 85
#define NHEADS 20
#define DHEAD 64
#define INNER (NHEADS*DHEAD)   // 1280

// ---------------- scratch (static device globals; no allocation) -------------
__device__ float g_q [BB*NQ*INNER];      // 168 MB
__device__ float g_k [BB*CTX*INNER];
__device__ float g_v [BB*CTX*INNER];
__device__ float g_ao[BB*NQ*INNER];      // 168 MB
__device__ unsigned char g_fg[BB*NQ];

// ---------------- mask: exact integer bicubic-threshold ----------------------
// scale=4 -> t=0.5 exactly; weights = [-3,19,19,-3]/32; resized!=0 <=> integer
// stencil sum != 0 (all reference float ops are exact multiples of 1/1024).
__global__ void mask_kernel(const int* __restrict__ mask)
{
    int idx = blockIdx.x * blockDim.x + threadIdx.x;
    if (idx >= BB*NQ) return;
    int b = idx / NQ, n = idx % NQ;
    int o = n >> 6, p = n & 63;
    const int iw[4] = {-3, 19, 19, -3};
    const int* mb = mask + (size_t)b * 256 * 256;
    int acc = 0;
#pragma unroll
    for (int s = 0; s < 4; s++) {
        const int* row = mb + (4*o + s) * 256 + 4*p;
        int rw = iw[s];
#pragma unroll
        for (int t = 0; t < 4; t++) acc += rw * iw[t] * row[t];
    }
    g_fg[idx] = (acc != 0) ? 1 : 0;
}

// ---------------- fp32 SGEMM: C[M,N] = A[M,K] @ B[K,N] (+bias) ---------------
// 128x128 tile, BK=16, 256 threads, 8x8 per thread.
__global__ void __launch_bounds__(256)
sgemm_kernel(const float* __restrict__ A, const float* __restrict__ Bm,
             const float* __restrict__ bias, float* __restrict__ C,
             int M, int N, int K)
{
    __shared__ float As[128][17];   // [m][k], padded
    __shared__ float Bs[16][128];   // [k][n]

    int tid = threadIdx.x;
    int tx = tid & 15, ty = tid >> 4;
    int brow = blockIdx.y * 128;
    int bcol = blockIdx.x * 128;

    float acc[8][8];
#pragma unroll
    for (int i = 0; i < 8; i++)
#pragma unroll
        for (int j = 0; j < 8; j++) acc[i][j] = 0.f;

    int a_row = tid >> 2;          // 0..63
    int a_col = (tid & 3) * 4;     // 0,4,8,12
    int b_row = tid >> 5;          // 0..7
    int b_col = (tid & 31) * 4;    // 0..124

    for (int k0 = 0; k0 < K; k0 += 16) {
#pragma unroll
        for (int s = 0; s < 2; s++) {
            int r  = a_row + 64*s;
            int gr = brow + r;
            float4 va = (gr < M) ? *(const float4*)(A + (size_t)gr*K + k0 + a_col)
                                 : make_float4(0.f,0.f,0.f,0.f);
            As[r][a_col+0] = va.x; As[r][a_col+1] = va.y;
            As[r][a_col+2] = va.z; As[r][a_col+3] = va.w;
        }
#pragma unroll
        for (int s = 0; s < 2; s++) {
            int r = b_row + 8*s;
            float4 vb = *(const float4*)(Bm + (size_t)(k0 + r)*N + bcol + b_col);
            *(float4*)(&Bs[r][b_col]) = vb;
        }
        __syncthreads();

#pragma unroll
        for (int k = 0; k < 16; k++) {
            float a[8], bvals[8];
#pragma unroll
            for (int i = 0; i < 8; i++) a[i] = As[ty*8 + i][k];
            float4 b0 = *(const float4*)(&Bs[k][tx*8]);
            float4 b1 = *(const float4*)(&Bs[k][tx*8 + 4]);
            bvals[0]=b0.x; bvals[1]=b0.y; bvals[2]=b0.z; bvals[3]=b0.w;
            bvals[4]=b1.x; bvals[5]=b1.y; bvals[6]=b1.z; bvals[7]=b1.w;
#pragma unroll
            for (int i = 0; i < 8; i++)
#pragma unroll
                for (int j = 0; j < 8; j++)
                    acc[i][j] += a[i] * bvals[j];
        }
        __syncthreads();
    }

#pragma unroll
    for (int i = 0; i < 8; i++) {
        int gr = brow + ty*8 + i;
        if (gr >= M) continue;
#pragma unroll
        for (int j = 0; j < 8; j += 4) {
            int gc = bcol + tx*8 + j;
            float4 v;
            v.x = acc[i][j];   v.y = acc[i][j+1];
            v.z = acc[i][j+2]; v.w = acc[i][j+3];
            if (bias) { v.x += bias[gc]; v.y += bias[gc+1];
                        v.z += bias[gc+2]; v.w += bias[gc+3]; }
            *(float4*)(C + (size_t)gr*N + gc) = v;
        }
    }
}

// ---------------- fused masked attention (85 keys, d=64) ---------------------
// grid (NQ/64, NHEADS, B); 256 threads = 8 warps, each warp does 8 queries.
__global__ void __launch_bounds__(256) attn_kernel()
{
    __shared__ float Ks[CTX*65];
    __shared__ float Vs[CTX*65];
    __shared__ float Ps[8][88];
    __shared__ float Qs[8][64];

    int b = blockIdx.z, h = blockIdx.y, it = blockIdx.x;
    int tid = threadIdx.x;
    int warp = tid >> 5, lane = tid & 31;

    const float* kbase = g_k + ((size_t)b*CTX)*INNER + h*DHEAD;
    const float* vbase = g_v + ((size_t)b*CTX)*INNER + h*DHEAD;
    for (int idx = tid; idx < CTX*DHEAD; idx += 256) {
        int j = idx >> 6, d = idx & 63;
        Ks[j*65 + d] = kbase[(size_t)j*INNER + d];
        Vs[j*65 + d] = vbase[(size_t)j*INNER + d];
    }
    __syncthreads();

    const float scale = 0.125f;   // 64^-0.5
    for (int qi = 0; qi < 8; qi++) {
        int i = it*64 + warp*8 + qi;
        const float* qp = g_q + ((size_t)b*NQ + i)*INNER + h*DHEAD;
        Qs[warp][lane]      = qp[lane];
        Qs[warp][lane + 32] = qp[lane + 32];
        __syncwarp();
        int fg = g_fg[b*NQ + i];

        float s[3];
        float mx = -FLT_MAX;
#pragma unroll
        for (int c = 0; c < 3; c++) {
            int j = lane + 32*c;
            float v = -FLT_MAX;
            if (j < CTX) {
                const float* kr = &Ks[j*65];
                float a = 0.f;
#pragma unroll
                for (int d = 0; d < 64; d++) a += Qs[warp][d] * kr[d];
                a *= scale;
                bool valid = (j < 77) || (j < 81 ? (fg != 0) : (fg == 0));
                v = valid ? a : -FLT_MAX;
            }
            s[c] = v;
            mx = fmaxf(mx, v);
        }
#pragma unroll
        for (int off = 16; off > 0; off >>= 1)
            mx = fmaxf(mx, __shfl_xor_sync(0xffffffffu, mx, off));

        float sum = 0.f;
#pragma unroll
        for (int c = 0; c < 3; c++) {
            int j = lane + 32*c;
            float p = (s[c] > -0.5f*FLT_MAX) ? expf(s[c] - mx) : 0.f;
            if (j < CTX) Ps[warp][j] = p;
            sum += p;
        }
#pragma unroll
        for (int off = 16; off > 0; off >>= 1)
            sum += __shfl_xor_sync(0xffffffffu, sum, off);
        float inv = 1.f / sum;
        __syncwarp();

        float o0 = 0.f, o1 = 0.f;
        for (int j = 0; j < CTX; j++) {
            float p = Ps[warp][j];
            o0 += p * Vs[j*65 + lane];
            o1 += p * Vs[j*65 + lane + 32];
        }
        float* op = g_ao + ((size_t)b*NQ + i)*INNER + h*DHEAD;
        op[lane]      = o0 * inv;
        op[lane + 32] = o1 * inv;
        __syncwarp();
    }
}

// ---------------- launch ------------------------------------------------------
extern "C" void kernel_launch(void* const* d_in, const int* in_sizes, int n_in,
                              void* d_out, int out_size)
{
    (void)in_sizes; (void)n_in; (void)out_size;
    const float* x    = (const float*)d_in[0];
    const float* ctxp = (const float*)d_in[1];
    const float* Wq   = (const float*)d_in[2];
    const float* Wk   = (const float*)d_in[3];
    const float* Wv   = (const float*)d_in[4];
    const float* Wo   = (const float*)d_in[5];
    const float* bo   = (const float*)d_in[6];
    const int*   mask = (const int*)d_in[7];
    float* out = (float*)d_out;

    float *q, *k, *v, *ao;
    cudaGetSymbolAddress((void**)&q,  g_q);
    cudaGetSymbolAddress((void**)&k,  g_k);
    cudaGetSymbolAddress((void**)&v,  g_v);
    cudaGetSymbolAddress((void**)&ao, g_ao);

    // 1. mask (exact integer stencil)
    mask_kernel<<<(BB*NQ + 255)/256, 256>>>(mask);

    // 2. K, V projections: [680,1024] @ [1024,1280]
    {
        dim3 grid(INNER/128, (BB*CTX + 127)/128);
        sgemm_kernel<<<grid, 256>>>(ctxp, Wk, nullptr, k, BB*CTX, INNER, CD);
        sgemm_kernel<<<grid, 256>>>(ctxp, Wv, nullptr, v, BB*CTX, INNER, CD);
    }

    // 3. Q projection: [32768,1280] @ [1280,1280]
    {
        dim3 grid(INNER/128, (BB*NQ)/128);
        sgemm_kernel<<<grid, 256>>>(x, Wq, nullptr, q, BB*NQ, INNER, QD);
    }

    // 4. fused masked attention
    {
        dim3 grid(NQ/64, NHEADS, BB);
        attn_kernel<<<grid, 256>>>();
    }

    // 5. output projection + bias: [32768,1280] @ [1280,1280] + bo
    {
        dim3 grid(QD/128, (BB*NQ)/128);
        sgemm_kernel<<<grid, 256>>>(ao, Wo, bo, out, BB*NQ, QD, INNER);
    }
}

// round 3
// speedup vs baseline: 1.9809x; 1.9809x over previous
#include <cuda_runtime.h>
#include <cuda_bf16.h>
#include <math.h>
#include <float.h>
#include <stdint.h>

#define BB 8
#define NQ 4096
#define QD 1280
#define CD 1024
#define CTX 85
#define NHEADS 20
#define DHEAD 64
#define INNER (NHEADS*DHEAD)   // 1280

typedef unsigned short ushort_t;

// ---------------- scratch (static device globals; no allocation) -------------
__device__ float g_q [(size_t)BB*NQ*INNER];          // fp32 Q (attn input)
__device__ float g_k [(size_t)BB*CTX*INNER];
__device__ float g_v [(size_t)BB*CTX*INNER];
__device__ __nv_bfloat16 g_xhi[(size_t)BB*NQ*QD];
__device__ __nv_bfloat16 g_xlo[(size_t)BB*NQ*QD];
__device__ __nv_bfloat16 g_ao_hi[(size_t)BB*NQ*INNER];
__device__ __nv_bfloat16 g_ao_lo[(size_t)BB*NQ*INNER];
__device__ __nv_bfloat16 g_wqt_hi[(size_t)INNER*QD];  // Wq^T [INNER][QD]
__device__ __nv_bfloat16 g_wqt_lo[(size_t)INNER*QD];
__device__ __nv_bfloat16 g_wot_hi[(size_t)QD*INNER];  // Wo^T [QD][INNER]
__device__ __nv_bfloat16 g_wot_lo[(size_t)QD*INNER];
__device__ unsigned char g_fg[BB*NQ];

// ============================ PTX helpers ====================================
__device__ __forceinline__ uint32_t smem_to_u32(const void* p) {
    uint32_t a;
    asm("{ .reg .u64 t; cvta.to.shared.u64 t, %1; cvt.u32.u64 %0, t; }"
        : "=r"(a) : "l"(p));
    return a;
}

#if defined(__CUDA_ARCH_FEAT_SM103_ALL)
#define HAS_TCGEN05 1
#else
#define HAS_TCGEN05 0
#endif

#if HAS_TCGEN05
__device__ __forceinline__ uint32_t elect_one_pred() {
    uint32_t pred;
    asm volatile(
        "{\n\t.reg .pred p;\n\t"
        "elect.sync _|p, 0xFFFFFFFF;\n\t"
        "selp.b32 %0, 1, 0, p;\n\t}"
        : "=r"(pred));
    return pred;
}
#define TCGEN05_ALLOC(sa, n) \
    asm volatile("tcgen05.alloc.cta_group::1.sync.aligned.shared::cta.b32 [%0], %1;" \
        :: "r"((uint32_t)(sa)), "r"((uint32_t)(n)) : "memory")
#define TCGEN05_DEALLOC(t, n) \
    asm volatile("tcgen05.dealloc.cta_group::1.sync.aligned.b32 %0, %1;" :: "r"(t), "r"((uint32_t)(n)))
#define TCGEN05_RELINQ() \
    asm volatile("tcgen05.relinquish_alloc_permit.cta_group::1.sync.aligned;")
#define TCGEN05_COMMIT(mb) \
    asm volatile("tcgen05.commit.cta_group::1.mbarrier::arrive::one.shared::cluster.b64 [%0];" \
        :: "r"((uint32_t)(mb)) : "memory")
#define TCGEN05_FENCE_AFTER() asm volatile("tcgen05.fence::after_thread_sync;" ::: "memory")
#define TCGEN05_FENCE_BEFORE() asm volatile("tcgen05.fence::before_thread_sync;" ::: "memory")
#define TCGEN05_WAIT_LD() asm volatile("tcgen05.wait::ld.sync.aligned;" ::: "memory")
#define MBARRIER_INIT(mb, c) \
    asm volatile("mbarrier.init.shared.b64 [%0], %1;" :: "r"((uint32_t)(mb)), "r"((uint32_t)(c)) : "memory")
#define MBARRIER_WAIT_PARITY(mb, ph) do { \
    uint32_t _m = (uint32_t)(mb), _p = (uint32_t)(ph), _d; \
    asm volatile("{\n\t.reg .pred p;\n\t" \
        "mbarrier.try_wait.parity.acquire.cta.shared::cta.b64 p, [%1], %2;\n\t" \
        "selp.b32 %0, 1, 0, p;\n\t}" : "=r"(_d) : "r"(_m), "r"(_p) : "memory"); \
    if (!_d) { \
        asm volatile("{\n\t.reg .pred P1;\n\t" \
            "WL_%=:\n\t" \
            "mbarrier.try_wait.parity.acquire.cta.shared::cta.b64 P1, [%0], %1, 0x989680;\n\t" \
            "@P1 bra.uni WD_%=;\n\t" \
            "bra.uni WL_%=;\n\t" \
            "WD_%=:\n\t}" :: "r"(_m), "r"(_p) : "memory"); \
    } \
} while (0)
#define TCGEN05_LD_32X32B_X32(r, ta) \
    asm volatile("tcgen05.ld.sync.aligned.32x32b.x32.b32 " \
        "{%0, %1, %2, %3, %4, %5, %6, %7, %8, %9, %10, %11, %12, %13, %14, %15, " \
        " %16, %17, %18, %19, %20, %21, %22, %23, %24, %25, %26, %27, %28, %29, %30, %31}, [%32];" \
        : "=r"((r)[0]),  "=r"((r)[1]),  "=r"((r)[2]),  "=r"((r)[3]), \
          "=r"((r)[4]),  "=r"((r)[5]),  "=r"((r)[6]),  "=r"((r)[7]), \
          "=r"((r)[8]),  "=r"((r)[9]),  "=r"((r)[10]), "=r"((r)[11]), \
          "=r"((r)[12]), "=r"((r)[13]), "=r"((r)[14]), "=r"((r)[15]), \
          "=r"((r)[16]), "=r"((r)[17]), "=r"((r)[18]), "=r"((r)[19]), \
          "=r"((r)[20]), "=r"((r)[21]), "=r"((r)[22]), "=r"((r)[23]), \
          "=r"((r)[24]), "=r"((r)[25]), "=r"((r)[26]), "=r"((r)[27]), \
          "=r"((r)[28]), "=r"((r)[29]), "=r"((r)[30]), "=r"((r)[31]) \
        : "r"(ta))

__device__ __forceinline__ void mma_f16_ss(uint32_t d_tmem, uint64_t a_desc,
                                           uint64_t b_desc, uint32_t idesc, bool acc)
{
    uint32_t en = acc ? 1u : 0u;
    asm volatile(
        "{\n\t.reg .pred p;\n\t"
        "setp.ne.u32 p, %5, 0;\n\t"
        "tcgen05.mma.cta_group::1.kind::f16 [%0], %1, %2, %3, {%4, %4, %4, %4}, p;\n\t}"
        :: "r"(d_tmem), "l"(a_desc), "l"(b_desc), "r"(idesc), "r"(0u), "r"(en)
        : "memory");
}
#endif // HAS_TCGEN05

static constexpr uint64_t SMEM_DESC_BASE_SW128 =
    (uint64_t(2)  << 61) | (uint64_t(1) << 46) | (uint64_t(64) << 32) | (uint64_t(1) << 16);
#define MAKE_SMEM_DESC(ba) (SMEM_DESC_BASE_SW128 | ((uint64_t)((ba) >> 4) & 0x3FFF))
#define SMEM_SWIZZLE_128B(bo) ((bo) ^ (((bo) >> 3) & 0x70))

// ---------------- mask: exact integer bicubic-threshold ----------------------
__global__ void mask_kernel(const int* __restrict__ mask)
{
    int idx = blockIdx.x * blockDim.x + threadIdx.x;
    if (idx >= BB*NQ) return;
    int b = idx / NQ, n = idx % NQ;
    int o = n >> 6, p = n & 63;
    const int iw[4] = {-3, 19, 19, -3};
    const int* mb = mask + (size_t)b * 256 * 256;
    int acc = 0;
#pragma unroll
    for (int s = 0; s < 4; s++) {
        const int* row = mb + (4*o + s) * 256 + 4*p;
        int rw = iw[s];
#pragma unroll
        for (int t = 0; t < 4; t++) acc += rw * iw[t] * row[t];
    }
    g_fg[idx] = (acc != 0) ? 1 : 0;
}

// ---------------- weight transpose + bf16 split -------------------------------
__global__ void wtrans_kernel(const float* __restrict__ W,
                              __nv_bfloat16* __restrict__ Thi,
                              __nv_bfloat16* __restrict__ Tlo, int K, int N)
{
    __shared__ float t[32][33];
    int k0 = blockIdx.x * 32, n0 = blockIdx.y * 32;
    int tx = threadIdx.x, ty = threadIdx.y;
    for (int r = ty; r < 32; r += 8)
        t[r][tx] = W[(size_t)(k0 + r)*N + n0 + tx];
    __syncthreads();
    for (int r = ty; r < 32; r += 8) {
        float v = t[tx][r];
        __nv_bfloat16 h = __float2bfloat16(v);
        __nv_bfloat16 l = __float2bfloat16(v - __bfloat162float(h));
        Thi[(size_t)(n0 + r)*K + k0 + tx] = h;
        Tlo[(size_t)(n0 + r)*K + k0 + tx] = l;
    }
}

// ---------------- elementwise fp32 -> bf16 hi/lo split ------------------------
__global__ void split_kernel(const float* __restrict__ X,
                             __nv_bfloat16* __restrict__ hi,
                             __nv_bfloat16* __restrict__ lo, int n4)
{
    int i = blockIdx.x * blockDim.x + threadIdx.x;
    if (i >= n4) return;
    float4 v = ((const float4*)X)[i];
    float a[4] = {v.x, v.y, v.z, v.w};
    ushort4 uh, ul;
    ushort_t* uhp = (ushort_t*)&uh;
    ushort_t* ulp = (ushort_t*)&ul;
#pragma unroll
    for (int e = 0; e < 4; e++) {
        __nv_bfloat16 h = __float2bfloat16(a[e]);
        __nv_bfloat16 l = __float2bfloat16(a[e] - __bfloat162float(h));
        uhp[e] = __bfloat16_as_ushort(h);
        ulp[e] = __bfloat16_as_ushort(l);
    }
    *(ushort4*)(hi + (size_t)4*i) = uh;
    *(ushort4*)(lo + (size_t)4*i) = ul;
}

// ---------------- fp32 SGEMM for small K/V projections ------------------------
__global__ void __launch_bounds__(256)
sgemm_kernel(const float* __restrict__ A, const float* __restrict__ Bm,
             const float* __restrict__ bias, float* __restrict__ C,
             int M, int N, int K)
{
    __shared__ float As[128][17];
    __shared__ float Bs[16][128];
    int tid = threadIdx.x;
    int tx = tid & 15, ty = tid >> 4;
    int brow = blockIdx.y * 128;
    int bcol = blockIdx.x * 128;
    float acc[8][8];
#pragma unroll
    for (int i = 0; i < 8; i++)
#pragma unroll
        for (int j = 0; j < 8; j++) acc[i][j] = 0.f;
    int a_row = tid >> 2, a_col = (tid & 3) * 4;
    int b_row = tid >> 5, b_col = (tid & 31) * 4;
    for (int k0 = 0; k0 < K; k0 += 16) {
#pragma unroll
        for (int s = 0; s < 2; s++) {
            int r = a_row + 64*s, gr = brow + r;
            float4 va = (gr < M) ? *(const float4*)(A + (size_t)gr*K + k0 + a_col)
                                 : make_float4(0.f,0.f,0.f,0.f);
            As[r][a_col+0]=va.x; As[r][a_col+1]=va.y; As[r][a_col+2]=va.z; As[r][a_col+3]=va.w;
        }
#pragma unroll
        for (int s = 0; s < 2; s++) {
            int r = b_row + 8*s;
            *(float4*)(&Bs[r][b_col]) = *(const float4*)(Bm + (size_t)(k0 + r)*N + bcol + b_col);
        }
        __syncthreads();
#pragma unroll
        for (int k = 0; k < 16; k++) {
            float a[8], bv[8];
#pragma unroll
            for (int i = 0; i < 8; i++) a[i] = As[ty*8 + i][k];
            float4 b0 = *(const float4*)(&Bs[k][tx*8]);
            float4 b1 = *(const float4*)(&Bs[k][tx*8 + 4]);
            bv[0]=b0.x; bv[1]=b0.y; bv[2]=b0.z; bv[3]=b0.w;
            bv[4]=b1.x; bv[5]=b1.y; bv[6]=b1.z; bv[7]=b1.w;
#pragma unroll
            for (int i = 0; i < 8; i++)
#pragma unroll
                for (int j = 0; j < 8; j++) acc[i][j] += a[i] * bv[j];
        }
        __syncthreads();
    }
#pragma unroll
    for (int i = 0; i < 8; i++) {
        int gr = brow + ty*8 + i;
        if (gr >= M) continue;
#pragma unroll
        for (int j = 0; j < 8; j += 4) {
            int gc = bcol + tx*8 + j;
            float4 v;
            v.x = acc[i][j]; v.y = acc[i][j+1]; v.z = acc[i][j+2]; v.w = acc[i][j+3];
            if (bias) { v.x += bias[gc]; v.y += bias[gc+1]; v.z += bias[gc+2]; v.w += bias[gc+3]; }
            *(float4*)(C + (size_t)gr*N + gc) = v;
        }
    }
}

// ================= bf16x3 tcgen05 GEMM: C = A@B^T (+bias) ====================
// A[M,K] as hi/lo bf16 row-major; Bt[N,K] as hi/lo bf16 row-major.
// Tile: BM=128 x BN=256, BK=64, double-buffered SMEM, TMEM fp32 accumulator.
#define G_BM 128
#define G_BN 256
#define G_BK 64
#define G_BUFSZ 98304      // (128+128+256+256) rows * 128B
#define G_SMEM  (2048 + 2*G_BUFSZ)   // 1KB header + 1KB align slack + buffers
#define G_IDESC 0x08400490u   // F32 acc, BF16xBF16, N=256, M=128

__global__ void __launch_bounds__(256)
gemm_bf16x3(const __nv_bfloat16* __restrict__ Ahi, const __nv_bfloat16* __restrict__ Alo,
            const __nv_bfloat16* __restrict__ Bhi, const __nv_bfloat16* __restrict__ Blo,
            const float* __restrict__ bias, float* __restrict__ C,
            int M, int N, int K)
{
#if HAS_TCGEN05
    extern __shared__ char smem[];
    const uint32_t sb = smem_to_u32(smem);
    const uint32_t ab = (sb + 1024 + 1023) & ~1023u;   // 1024-aligned buffer base
    char* abp = smem + (ab - sb);
    const int tid = threadIdx.x;
    const int wid = tid >> 5, lane = tid & 31;
    const int brow = blockIdx.y * G_BM;
    const int bcol = blockIdx.x * G_BN;

    if (wid == 0) TCGEN05_ALLOC(sb, 256);
    __syncthreads();
    uint32_t tmem;
    asm volatile("ld.shared.b32 %0, [%1];" : "=r"(tmem) : "r"(sb));
    if (wid == 0) TCGEN05_RELINQ();
    if (tid == 0) { MBARRIER_INIT(sb + 8, 1); MBARRIER_INIT(sb + 16, 1); }
    __syncthreads();

    const int KCH = K / G_BK;
    int par0 = 0, par1 = 0;

    for (int c = 0; c < KCH; ++c) {
        int p = c & 1;
        if (c >= 2) {
            if (p == 0) { MBARRIER_WAIT_PARITY(sb + 8, par0); par0 ^= 1; }
            else        { MBARRIER_WAIT_PARITY(sb + 16, par1); par1 ^= 1; }
        }
        char* base = abp + p * G_BUFSZ;
        const int k0 = c * G_BK;

        // A hi/lo: 128 rows x 8 vec16
        for (int u = tid; u < 1024; u += 256) {
            int row = u >> 3, v = u & 7;
            uint32_t so = SMEM_SWIZZLE_128B((uint32_t)(row*128 + v*16));
            *(uint4*)(base + so) =
                *(const uint4*)(Ahi + (size_t)(brow + row)*K + k0 + v*8);
            *(uint4*)(base + 16384 + so) =
                *(const uint4*)(Alo + (size_t)(brow + row)*K + k0 + v*8);
        }
        // B hi/lo: 256 rows x 8 vec16
        for (int u = tid; u < 2048; u += 256) {
            int row = u >> 3, v = u & 7;
            uint32_t so = SMEM_SWIZZLE_128B((uint32_t)(row*128 + v*16));
            *(uint4*)(base + 32768 + so) =
                *(const uint4*)(Bhi + (size_t)(bcol + row)*K + k0 + v*8);
            *(uint4*)(base + 65536 + so) =
                *(const uint4*)(Blo + (size_t)(bcol + row)*K + k0 + v*8);
        }
        __syncthreads();

        if (wid == 0 && elect_one_pred()) {
            asm volatile("fence.proxy.async.shared::cta;" ::: "memory");
            uint32_t bu = ab + p * G_BUFSZ;
            uint64_t dah = MAKE_SMEM_DESC(bu);
            uint64_t dal = MAKE_SMEM_DESC(bu + 16384);
            uint64_t dbh = MAKE_SMEM_DESC(bu + 32768);
            uint64_t dbl = MAKE_SMEM_DESC(bu + 65536);
#pragma unroll
            for (int ks = 0; ks < 4; ++ks)
                mma_f16_ss(tmem, dah + ks*2, dbh + ks*2, G_IDESC, !(c == 0 && ks == 0));
#pragma unroll
            for (int ks = 0; ks < 4; ++ks)
                mma_f16_ss(tmem, dah + ks*2, dbl + ks*2, G_IDESC, true);
#pragma unroll
            for (int ks = 0; ks < 4; ++ks)
                mma_f16_ss(tmem, dal + ks*2, dbh + ks*2, G_IDESC, true);
            TCGEN05_COMMIT(sb + 8 + p*8);
        }
    }
    // drain both buffers' final commits
    MBARRIER_WAIT_PARITY(sb + 8, par0);
    MBARRIER_WAIT_PARITY(sb + 16, par1);
    TCGEN05_FENCE_AFTER();

    if (wid < 4) {
        int row = brow + wid*32 + lane;
#pragma unroll
        for (int cb = 0; cb < G_BN/32; ++cb) {
            uint32_t r[32];
            TCGEN05_LD_32X32B_X32(r, tmem + cb*32);
            TCGEN05_WAIT_LD();
            int col0 = bcol + cb*32;
            float* cp = C + (size_t)row*N + col0;
            if (bias) {
#pragma unroll
                for (int i = 0; i < 32; ++i) cp[i] = __uint_as_float(r[i]) + bias[col0 + i];
            } else {
#pragma unroll
                for (int i = 0; i < 32; ++i) cp[i] = __uint_as_float(r[i]);
            }
        }
        TCGEN05_FENCE_BEFORE();
    }
    __syncthreads();
    if (wid == 0) TCGEN05_DEALLOC(tmem, 256);
#endif // HAS_TCGEN05
}

// ---------------- fused masked attention (85 keys, d=64) ---------------------
// 256 queries/block, one query per thread, q & o in registers, broadcast LDS.
#define ATTN_Q 256
#define ATTN_SMEM ((2*CTX*64 + ATTN_Q*85)*4)   // 130560 B

__global__ void __launch_bounds__(256) attn_kernel()
{
    extern __shared__ float sm[];
    float* Ks = sm;                   // [85][64]
    float* Vs = sm + CTX*64;          // [85][64]
    float* Ps = sm + 2*CTX*64;        // [256][85] (also Q staging [256][65])

    int b = blockIdx.z, h = blockIdx.y;
    int qb = blockIdx.x * ATTN_Q;
    int tid = threadIdx.x;

    for (int u = tid; u < CTX*16; u += 256) {
        int j = u >> 4, v = u & 15;
        size_t off = (size_t)(b*CTX + j)*INNER + h*DHEAD + v*4;
        *(float4*)(Ks + j*64 + v*4) = *(const float4*)(g_k + off);
        *(float4*)(Vs + j*64 + v*4) = *(const float4*)(g_v + off);
    }
    for (int u = tid; u < ATTN_Q*16; u += 256) {
        int r = u >> 4, v = u & 15;
        float4 qv = *(const float4*)(g_q + (size_t)(b*NQ + qb + r)*INNER + h*DHEAD + v*4);
        float* dst = Ps + r*65 + v*4;
        dst[0]=qv.x; dst[1]=qv.y; dst[2]=qv.z; dst[3]=qv.w;
    }
    int fg = g_fg[b*NQ + qb + tid];
    __syncthreads();

    float q[64];
    {
        const float* src = Ps + tid*65;
#pragma unroll
        for (int d = 0; d < 64; ++d) q[d] = src[d];
    }
    __syncthreads();

    float* ps = Ps + tid*85;
    float mx = -FLT_MAX;
    for (int j = 0; j < CTX; ++j) {
        const float4* kr = (const float4*)(Ks + j*64);
        float a = 0.f;
#pragma unroll
        for (int v = 0; v < 16; ++v) {
            float4 kv = kr[v];
            a += q[4*v+0]*kv.x; a += q[4*v+1]*kv.y;
            a += q[4*v+2]*kv.z; a += q[4*v+3]*kv.w;
        }
        a *= 0.125f;
        bool valid = (j < 77) || ((j < 81) ? (fg != 0) : (fg == 0));
        a = valid ? a : -FLT_MAX;
        ps[j] = a;
        mx = fmaxf(mx, a);
    }
    float sum = 0.f;
    for (int j = 0; j < CTX; ++j) {
        float v = ps[j];
        float e = (v > -3.0e38f) ? __expf(v - mx) : 0.f;
        ps[j] = e;
        sum += e;
    }
    float inv = 1.f / sum;

    float o[64];
#pragma unroll
    for (int d = 0; d < 64; ++d) o[d] = 0.f;
    for (int j = 0; j < CTX; ++j) {
        float pp = ps[j];
        const float4* vr = (const float4*)(Vs + j*64);
#pragma unroll
        for (int v = 0; v < 16; ++v) {
            float4 vv = vr[v];
            o[4*v+0] += pp*vv.x; o[4*v+1] += pp*vv.y;
            o[4*v+2] += pp*vv.z; o[4*v+3] += pp*vv.w;
        }
    }
    size_t obase = (size_t)(b*NQ + qb + tid)*INNER + h*DHEAD;
#pragma unroll
    for (int v = 0; v < 16; ++v) {
        ushort4 uh, ul;
        ushort_t* uhp = (ushort_t*)&uh;
        ushort_t* ulp = (ushort_t*)&ul;
#pragma unroll
        for (int e = 0; e < 4; ++e) {
            float f = o[4*v+e] * inv;
            __nv_bfloat16 hh = __float2bfloat16(f);
            __nv_bfloat16 ll = __float2bfloat16(f - __bfloat162float(hh));
            uhp[e] = __bfloat16_as_ushort(hh);
            ulp[e] = __bfloat16_as_ushort(ll);
        }
        *(ushort4*)(g_ao_hi + obase + v*4) = uh;
        *(ushort4*)(g_ao_lo + obase + v*4) = ul;
    }
}

// ---------------- launch ------------------------------------------------------
extern "C" void kernel_launch(void* const* d_in, const int* in_sizes, int n_in,
                              void* d_out, int out_size)
{
    (void)in_sizes; (void)n_in; (void)out_size;
    const float* x    = (const float*)d_in[0];
    const float* ctxp = (const float*)d_in[1];
    const float* Wq   = (const float*)d_in[2];
    const float* Wk   = (const float*)d_in[3];
    const float* Wv   = (const float*)d_in[4];
    const float* Wo   = (const float*)d_in[5];
    const float* bo   = (const float*)d_in[6];
    const int*   mask = (const int*)d_in[7];
    float* out = (float*)d_out;

    float *q, *k, *v;
    __nv_bfloat16 *xhi, *xlo, *aohi, *aolo, *wqth, *wqtl, *woth, *wotl;
    cudaGetSymbolAddress((void**)&q,    g_q);
    cudaGetSymbolAddress((void**)&k,    g_k);
    cudaGetSymbolAddress((void**)&v,    g_v);
    cudaGetSymbolAddress((void**)&xhi,  g_xhi);
    cudaGetSymbolAddress((void**)&xlo,  g_xlo);
    cudaGetSymbolAddress((void**)&aohi, g_ao_hi);
    cudaGetSymbolAddress((void**)&aolo, g_ao_lo);
    cudaGetSymbolAddress((void**)&wqth, g_wqt_hi);
    cudaGetSymbolAddress((void**)&wqtl, g_wqt_lo);
    cudaGetSymbolAddress((void**)&woth, g_wot_hi);
    cudaGetSymbolAddress((void**)&wotl, g_wot_lo);

    cudaFuncSetAttribute(gemm_bf16x3, cudaFuncAttributeMaxDynamicSharedMemorySize, G_SMEM);
    cudaFuncSetAttribute(attn_kernel, cudaFuncAttributeMaxDynamicSharedMemorySize, ATTN_SMEM);

    // 1. mask
    mask_kernel<<<(BB*NQ + 255)/256, 256>>>(mask);

    // 2. weight transpose + split
    {
        dim3 blk(32, 8);
        wtrans_kernel<<<dim3(QD/32, INNER/32), blk>>>(Wq, wqth, wqtl, QD, INNER);
        wtrans_kernel<<<dim3(INNER/32, QD/32), blk>>>(Wo, woth, wotl, INNER, QD);
    }

    // 3. x -> bf16 hi/lo
    {
        int n4 = BB*NQ*QD/4;
        split_kernel<<<(n4 + 255)/256, 256>>>(x, xhi, xlo, n4);
    }

    // 4. K, V projections (fp32, small)
    {
        dim3 grid(INNER/128, (BB*CTX + 127)/128);
        sgemm_kernel<<<grid, 256>>>(ctxp, Wk, nullptr, k, BB*CTX, INNER, CD);
        sgemm_kernel<<<grid, 256>>>(ctxp, Wv, nullptr, v, BB*CTX, INNER, CD);
    }

    // 5. Q projection on tensor cores: [32768,1280] x [1280,1280]
    gemm_bf16x3<<<dim3(INNER/G_BN, (BB*NQ)/G_BM), 256, G_SMEM>>>(
        xhi, xlo, wqth, wqtl, nullptr, q, BB*NQ, INNER, QD);

    // 6. fused masked attention (writes bf16 hi/lo directly)
    attn_kernel<<<dim3(NQ/ATTN_Q, NHEADS, BB), 256, ATTN_SMEM>>>();

    // 7. output projection + bias on tensor cores
    gemm_bf16x3<<<dim3(QD/G_BN, (BB*NQ)/G_BM), 256, G_SMEM>>>(
        aohi, aolo, woth, wotl, bo, out, BB*NQ, QD, INNER);
}

// round 4
// speedup vs baseline: 2.4744x; 1.2491x over previous
#include <cuda_runtime.h>
#include <cuda_bf16.h>
#include <math.h>
#include <float.h>
#include <stdint.h>

#define BB 8
#define NQ 4096
#define QD 1280
#define CD 1024
#define CTX 85
#define NHEADS 20
#define DHEAD 64
#define INNER (NHEADS*DHEAD)   // 1280
#define MKV 768                // padded context rows (8*85=680 -> 768)
#define NBH (BB*NHEADS)        // 160

typedef unsigned short ushort_t;

// ---------------- scratch (static device globals; no allocation) -------------
__device__ float g_k [(size_t)MKV*INNER];
__device__ float g_v [(size_t)MKV*INNER];
__device__ __nv_bfloat16 g_xhi[(size_t)BB*NQ*QD];
__device__ __nv_bfloat16 g_xlo[(size_t)BB*NQ*QD];
__device__ __nv_bfloat16 g_chi[(size_t)MKV*CD];
__device__ __nv_bfloat16 g_clo[(size_t)MKV*CD];
__device__ __nv_bfloat16 g_qhi[(size_t)BB*NQ*INNER];
__device__ __nv_bfloat16 g_qlo[(size_t)BB*NQ*INNER];
__device__ __nv_bfloat16 g_ao_hi[(size_t)BB*NQ*INNER];
__device__ __nv_bfloat16 g_ao_lo[(size_t)BB*NQ*INNER];
__device__ __nv_bfloat16 g_wqt_hi[(size_t)INNER*QD];
__device__ __nv_bfloat16 g_wqt_lo[(size_t)INNER*QD];
__device__ __nv_bfloat16 g_wkt_hi[(size_t)INNER*CD];
__device__ __nv_bfloat16 g_wkt_lo[(size_t)INNER*CD];
__device__ __nv_bfloat16 g_wvt_hi[(size_t)INNER*CD];
__device__ __nv_bfloat16 g_wvt_lo[(size_t)INNER*CD];
__device__ __nv_bfloat16 g_wot_hi[(size_t)QD*INNER];
__device__ __nv_bfloat16 g_wot_lo[(size_t)QD*INNER];
// K / V^T SMEM-images (swizzle baked in), per (b,h)
__device__ __nv_bfloat16 g_kimg_hi[(size_t)NBH*96*64];
__device__ __nv_bfloat16 g_kimg_lo[(size_t)NBH*96*64];
__device__ __nv_bfloat16 g_vimg_hi[(size_t)NBH*64*128];
__device__ __nv_bfloat16 g_vimg_lo[(size_t)NBH*64*128];
__device__ unsigned char g_fg[BB*NQ];

// ============================ PTX helpers ====================================
__device__ __forceinline__ uint32_t smem_to_u32(const void* p) {
    uint32_t a;
    asm("{ .reg .u64 t; cvta.to.shared.u64 t, %1; cvt.u32.u64 %0, t; }"
        : "=r"(a) : "l"(p));
    return a;
}

#if defined(__CUDA_ARCH_FEAT_SM103_ALL)
#define HAS_TCGEN05 1
#else
#define HAS_TCGEN05 0
#endif

#if HAS_TCGEN05
__device__ __forceinline__ uint32_t elect_one_pred() {
    uint32_t pred;
    asm volatile(
        "{\n\t.reg .pred p;\n\t"
        "elect.sync _|p, 0xFFFFFFFF;\n\t"
        "selp.b32 %0, 1, 0, p;\n\t}"
        : "=r"(pred));
    return pred;
}
#define TCGEN05_ALLOC(sa, n) \
    asm volatile("tcgen05.alloc.cta_group::1.sync.aligned.shared::cta.b32 [%0], %1;" \
        :: "r"((uint32_t)(sa)), "r"((uint32_t)(n)) : "memory")
#define TCGEN05_DEALLOC(t, n) \
    asm volatile("tcgen05.dealloc.cta_group::1.sync.aligned.b32 %0, %1;" :: "r"(t), "r"((uint32_t)(n)))
#define TCGEN05_RELINQ() \
    asm volatile("tcgen05.relinquish_alloc_permit.cta_group::1.sync.aligned;")
#define TCGEN05_COMMIT(mb) \
    asm volatile("tcgen05.commit.cta_group::1.mbarrier::arrive::one.shared::cluster.b64 [%0];" \
        :: "r"((uint32_t)(mb)) : "memory")
#define TCGEN05_FENCE_AFTER() asm volatile("tcgen05.fence::after_thread_sync;" ::: "memory")
#define TCGEN05_FENCE_BEFORE() asm volatile("tcgen05.fence::before_thread_sync;" ::: "memory")
#define TCGEN05_WAIT_LD() asm volatile("tcgen05.wait::ld.sync.aligned;" ::: "memory")
#define FENCE_ASYNC() asm volatile("fence.proxy.async.shared::cta;" ::: "memory")
#define MBARRIER_INIT(mb, c) \
    asm volatile("mbarrier.init.shared.b64 [%0], %1;" :: "r"((uint32_t)(mb)), "r"((uint32_t)(c)) : "memory")
#define MBARRIER_WAIT_PARITY(mb, ph) do { \
    uint32_t _m = (uint32_t)(mb), _p = (uint32_t)(ph), _d; \
    asm volatile("{\n\t.reg .pred p;\n\t" \
        "mbarrier.try_wait.parity.acquire.cta.shared::cta.b64 p, [%1], %2;\n\t" \
        "selp.b32 %0, 1, 0, p;\n\t}" : "=r"(_d) : "r"(_m), "r"(_p) : "memory"); \
    if (!_d) { \
        asm volatile("{\n\t.reg .pred P1;\n\t" \
            "WL_%=:\n\t" \
            "mbarrier.try_wait.parity.acquire.cta.shared::cta.b64 P1, [%0], %1, 0x989680;\n\t" \
            "@P1 bra.uni WD_%=;\n\t" \
            "bra.uni WL_%=;\n\t" \
            "WD_%=:\n\t}" :: "r"(_m), "r"(_p) : "memory"); \
    } \
} while (0)
#define TCGEN05_LD_32X32B_X32(r, ta) \
    asm volatile("tcgen05.ld.sync.aligned.32x32b.x32.b32 " \
        "{%0, %1, %2, %3, %4, %5, %6, %7, %8, %9, %10, %11, %12, %13, %14, %15, " \
        " %16, %17, %18, %19, %20, %21, %22, %23, %24, %25, %26, %27, %28, %29, %30, %31}, [%32];" \
        : "=r"((r)[0]),  "=r"((r)[1]),  "=r"((r)[2]),  "=r"((r)[3]), \
          "=r"((r)[4]),  "=r"((r)[5]),  "=r"((r)[6]),  "=r"((r)[7]), \
          "=r"((r)[8]),  "=r"((r)[9]),  "=r"((r)[10]), "=r"((r)[11]), \
          "=r"((r)[12]), "=r"((r)[13]), "=r"((r)[14]), "=r"((r)[15]), \
          "=r"((r)[16]), "=r"((r)[17]), "=r"((r)[18]), "=r"((r)[19]), \
          "=r"((r)[20]), "=r"((r)[21]), "=r"((r)[22]), "=r"((r)[23]), \
          "=r"((r)[24]), "=r"((r)[25]), "=r"((r)[26]), "=r"((r)[27]), \
          "=r"((r)[28]), "=r"((r)[29]), "=r"((r)[30]), "=r"((r)[31]) \
        : "r"(ta))

__device__ __forceinline__ void mma_f16_ss(uint32_t d_tmem, uint64_t a_desc,
                                           uint64_t b_desc, uint32_t idesc, bool acc)
{
    uint32_t en = acc ? 1u : 0u;
    asm volatile(
        "{\n\t.reg .pred p;\n\t"
        "setp.ne.u32 p, %5, 0;\n\t"
        "tcgen05.mma.cta_group::1.kind::f16 [%0], %1, %2, %3, {%4, %4, %4, %4}, p;\n\t}"
        :: "r"(d_tmem), "l"(a_desc), "l"(b_desc), "r"(idesc), "r"(0u), "r"(en)
        : "memory");
}
#endif // HAS_TCGEN05

static constexpr uint64_t SMEM_DESC_BASE_SW128 =
    (uint64_t(2)  << 61) | (uint64_t(1) << 46) | (uint64_t(64) << 32) | (uint64_t(1) << 16);
#define MAKE_SMEM_DESC(ba) (SMEM_DESC_BASE_SW128 | ((uint64_t)((ba) >> 4) & 0x3FFF))
#define SMEM_SWIZZLE_128B(bo) ((bo) ^ (((bo) >> 3) & 0x70))

__device__ __forceinline__ void bf16split(float f, ushort_t& h, ushort_t& l)
{
    __nv_bfloat16 hh = __float2bfloat16(f);
    __nv_bfloat16 ll = __float2bfloat16(f - __bfloat162float(hh));
    h = __bfloat16_as_ushort(hh);
    l = __bfloat16_as_ushort(ll);
}

// ---------------- mask: exact integer bicubic-threshold ----------------------
__global__ void mask_kernel(const int* __restrict__ mask)
{
    int idx = blockIdx.x * blockDim.x + threadIdx.x;
    if (idx >= BB*NQ) return;
    int b = idx / NQ, n = idx % NQ;
    int o = n >> 6, p = n & 63;
    const int iw[4] = {-3, 19, 19, -3};
    const int* mb = mask + (size_t)b * 256 * 256;
    int acc = 0;
#pragma unroll
    for (int s = 0; s < 4; s++) {
        const int* row = mb + (4*o + s) * 256 + 4*p;
        int rw = iw[s];
#pragma unroll
        for (int t = 0; t < 4; t++) acc += rw * iw[t] * row[t];
    }
    g_fg[idx] = (acc != 0) ? 1 : 0;
}

// ---------------- weight transpose + bf16 split -------------------------------
__global__ void wtrans_kernel(const float* __restrict__ W,
                              __nv_bfloat16* __restrict__ Thi,
                              __nv_bfloat16* __restrict__ Tlo, int K, int N)
{
    __shared__ float t[32][33];
    int k0 = blockIdx.x * 32, n0 = blockIdx.y * 32;
    int tx = threadIdx.x, ty = threadIdx.y;
    for (int r = ty; r < 32; r += 8)
        t[r][tx] = W[(size_t)(k0 + r)*N + n0 + tx];
    __syncthreads();
    for (int r = ty; r < 32; r += 8) {
        float v = t[tx][r];
        ushort_t h, l; bf16split(v, h, l);
        Thi[(size_t)(n0 + r)*K + k0 + tx] = __ushort_as_bfloat16(h);
        Tlo[(size_t)(n0 + r)*K + k0 + tx] = __ushort_as_bfloat16(l);
    }
}

// ---------------- elementwise fp32 -> bf16 hi/lo split (w/ zero pad) ----------
__global__ void split_kernel(const float* __restrict__ X,
                             __nv_bfloat16* __restrict__ hi,
                             __nv_bfloat16* __restrict__ lo,
                             int n4_total, int n4_valid)
{
    int i = blockIdx.x * blockDim.x + threadIdx.x;
    if (i >= n4_total) return;
    float4 v = (i < n4_valid) ? ((const float4*)X)[i] : make_float4(0.f,0.f,0.f,0.f);
    float a[4] = {v.x, v.y, v.z, v.w};
    ushort4 uh, ul;
    ushort_t* uhp = (ushort_t*)&uh;
    ushort_t* ulp = (ushort_t*)&ul;
#pragma unroll
    for (int e = 0; e < 4; e++) bf16split(a[e], uhp[e], ulp[e]);
    *(ushort4*)(hi + (size_t)4*i) = uh;
    *(ushort4*)(lo + (size_t)4*i) = ul;
}

// ================= bf16x3 tcgen05 GEMM: C = A@B^T (+bias) ====================
#define G_BM 128
#define G_BN 256
#define G_BK 64
#define G_BUFSZ 98304
#define G_SMEM  (2048 + 2*G_BUFSZ)
#define G_IDESC 0x08400490u   // F32 acc, BF16xBF16, N=256, M=128

__global__ void __launch_bounds__(256)
gemm_bf16x3(const __nv_bfloat16* __restrict__ Ahi, const __nv_bfloat16* __restrict__ Alo,
            const __nv_bfloat16* __restrict__ Bhi, const __nv_bfloat16* __restrict__ Blo,
            const float* __restrict__ bias, float* __restrict__ C,
            __nv_bfloat16* __restrict__ Chi, __nv_bfloat16* __restrict__ Clo,
            int M, int N, int K)
{
#if HAS_TCGEN05
    extern __shared__ char smem[];
    const uint32_t sb = smem_to_u32(smem);
    const uint32_t ab = (sb + 1024 + 1023) & ~1023u;
    char* abp = smem + (ab - sb);
    const int tid = threadIdx.x;
    const int wid = tid >> 5, lane = tid & 31;
    const int brow = blockIdx.y * G_BM;
    const int bcol = blockIdx.x * G_BN;

    if (wid == 0) TCGEN05_ALLOC(sb, 256);
    __syncthreads();
    uint32_t tmem;
    asm volatile("ld.shared.b32 %0, [%1];" : "=r"(tmem) : "r"(sb));
    if (wid == 0) TCGEN05_RELINQ();
    if (tid == 0) { MBARRIER_INIT(sb + 8, 1); MBARRIER_INIT(sb + 16, 1); }
    __syncthreads();

    const int KCH = K / G_BK;
    int par0 = 0, par1 = 0;

    for (int c = 0; c < KCH; ++c) {
        int p = c & 1;
        if (c >= 2) {
            if (p == 0) { MBARRIER_WAIT_PARITY(sb + 8, par0); par0 ^= 1; }
            else        { MBARRIER_WAIT_PARITY(sb + 16, par1); par1 ^= 1; }
        }
        char* base = abp + p * G_BUFSZ;
        const int k0 = c * G_BK;

        for (int u = tid; u < 1024; u += 256) {
            int row = u >> 3, v = u & 7;
            uint32_t so = SMEM_SWIZZLE_128B((uint32_t)(row*128 + v*16));
            *(uint4*)(base + so) =
                *(const uint4*)(Ahi + (size_t)(brow + row)*K + k0 + v*8);
            *(uint4*)(base + 16384 + so) =
                *(const uint4*)(Alo + (size_t)(brow + row)*K + k0 + v*8);
        }
        for (int u = tid; u < 2048; u += 256) {
            int row = u >> 3, v = u & 7;
            uint32_t so = SMEM_SWIZZLE_128B((uint32_t)(row*128 + v*16));
            *(uint4*)(base + 32768 + so) =
                *(const uint4*)(Bhi + (size_t)(bcol + row)*K + k0 + v*8);
            *(uint4*)(base + 65536 + so) =
                *(const uint4*)(Blo + (size_t)(bcol + row)*K + k0 + v*8);
        }
        __syncthreads();

        if (wid == 0 && elect_one_pred()) {
            FENCE_ASYNC();
            uint32_t bu = ab + p * G_BUFSZ;
            uint64_t dah = MAKE_SMEM_DESC(bu);
            uint64_t dal = MAKE_SMEM_DESC(bu + 16384);
            uint64_t dbh = MAKE_SMEM_DESC(bu + 32768);
            uint64_t dbl = MAKE_SMEM_DESC(bu + 65536);
#pragma unroll
            for (int ks = 0; ks < 4; ++ks)
                mma_f16_ss(tmem, dah + ks*2, dbh + ks*2, G_IDESC, !(c == 0 && ks == 0));
#pragma unroll
            for (int ks = 0; ks < 4; ++ks)
                mma_f16_ss(tmem, dah + ks*2, dbl + ks*2, G_IDESC, true);
#pragma unroll
            for (int ks = 0; ks < 4; ++ks)
                mma_f16_ss(tmem, dal + ks*2, dbh + ks*2, G_IDESC, true);
            TCGEN05_COMMIT(sb + 8 + p*8);
        }
    }
    MBARRIER_WAIT_PARITY(sb + 8, par0);
    MBARRIER_WAIT_PARITY(sb + 16, par1);
    TCGEN05_FENCE_AFTER();

    if (wid < 4) {
        int row = brow + wid*32 + lane;
#pragma unroll
        for (int cb = 0; cb < G_BN/32; ++cb) {
            uint32_t r[32];
            TCGEN05_LD_32X32B_X32(r, tmem + cb*32);
            TCGEN05_WAIT_LD();
            int col0 = bcol + cb*32;
            if (Chi) {   // bf16 hi/lo split output
                uint32_t hp[16], lp[16];
#pragma unroll
                for (int m = 0; m < 16; ++m) {
                    ushort_t h0, l0, h1, l1;
                    bf16split(__uint_as_float(r[2*m]),   h0, l0);
                    bf16split(__uint_as_float(r[2*m+1]), h1, l1);
                    hp[m] = ((uint32_t)h1 << 16) | h0;
                    lp[m] = ((uint32_t)l1 << 16) | l0;
                }
                uint32_t* dh = (uint32_t*)(Chi + (size_t)row*N + col0);
                uint32_t* dl = (uint32_t*)(Clo + (size_t)row*N + col0);
#pragma unroll
                for (int m = 0; m < 16; ++m) { dh[m] = hp[m]; dl[m] = lp[m]; }
            } else {
                float* cp = C + (size_t)row*N + col0;
                if (bias) {
#pragma unroll
                    for (int i = 0; i < 32; ++i) cp[i] = __uint_as_float(r[i]) + bias[col0 + i];
                } else {
#pragma unroll
                    for (int i = 0; i < 32; ++i) cp[i] = __uint_as_float(r[i]);
                }
            }
        }
        TCGEN05_FENCE_BEFORE();
    }
    __syncthreads();
    if (wid == 0) TCGEN05_DEALLOC(tmem, 256);
#endif
}

// ---------------- K / V^T image bake (swizzled SMEM images) -------------------
__global__ void __launch_bounds__(128) kv_image_kernel()
{
    int bh = blockIdx.x;
    int b = bh / NHEADS, h = bh % NHEADS;
    int tid = threadIdx.x;
    char* kh = (char*)(g_kimg_hi + (size_t)bh*96*64);
    char* kl = (char*)(g_kimg_lo + (size_t)bh*96*64);
    char* vh = (char*)(g_vimg_hi + (size_t)bh*64*128);
    char* vl = (char*)(g_vimg_lo + (size_t)bh*64*128);

    // K image: [96 rows(j) x 64 cols(d)], SW128 rows of 128B
    for (int u = tid; u < 96*64; u += 128) {
        int j = u >> 6, d = u & 63;
        float f = (j < CTX) ? g_k[(size_t)(b*CTX + j)*INNER + h*DHEAD + d] : 0.f;
        ushort_t hh, ll; bf16split(f, hh, ll);
        uint32_t so = SMEM_SWIZZLE_128B((uint32_t)(j*128 + d*2));
        *(ushort_t*)(kh + so) = hh;
        *(ushort_t*)(kl + so) = ll;
    }
    // V^T image: [64 rows(d) x 128 cols(j)], blocked atoms (8 atom-rows, 2 atom-cols)
    for (int u = tid; u < 64*128; u += 128) {
        int d = u >> 7, j = u & 127;
        float f = (j < CTX) ? g_v[(size_t)(b*CTX + j)*INNER + h*DHEAD + d] : 0.f;
        ushort_t hh, ll; bf16split(f, hh, ll);
        uint32_t addr = (uint32_t)(((d >> 3) + (j >> 6)*8)*1024 + (d & 7)*128 + (j & 63)*2);
        uint32_t so = SMEM_SWIZZLE_128B(addr);
        *(ushort_t*)(vh + so) = hh;
        *(ushort_t*)(vl + so) = ll;
    }
}

// ---------------- tcgen05 fused masked attention ------------------------------
// grid (8, 20, 8): (qgroup, h, b). 128 threads. 4 q-tiles of 128 per CTA.
#define ATT_QT 4
#define A_QHI 0
#define A_QLO 16384
#define A_KHI 32768
#define A_KLO 45056
#define A_VHI 57344
#define A_VLO 73728
#define A_PHI 90112
#define A_PLO 122880
#define ATTN_SMEM (2048 + 155648)
#define IDESC_S 0x08180490u   // M=128, N=96, bf16, f32 acc
#define IDESC_O 0x08100490u   // M=128, N=64

__global__ void __launch_bounds__(128) attn_tc()
{
#if HAS_TCGEN05
    extern __shared__ char smem[];
    const uint32_t sb = smem_to_u32(smem);
    const uint32_t ab = (sb + 1024 + 1023) & ~1023u;
    char* abp = smem + (ab - sb);
    int tid = threadIdx.x, wid = tid >> 5;
    int b = blockIdx.z, h = blockIdx.y, qg = blockIdx.x;
    int bh = b*NHEADS + h;

    if (wid == 0) TCGEN05_ALLOC(sb, 256);
    __syncthreads();
    uint32_t tmem;
    asm volatile("ld.shared.b32 %0, [%1];" : "=r"(tmem) : "r"(sb));
    if (wid == 0) TCGEN05_RELINQ();
    if (tid == 0) { MBARRIER_INIT(sb + 8, 1); MBARRIER_INIT(sb + 16, 1); }
    __syncthreads();

    // load K / V^T images (flat copy; swizzle baked in)
    {
        const uint4* skh = (const uint4*)(g_kimg_hi + (size_t)bh*96*64);
        const uint4* skl = (const uint4*)(g_kimg_lo + (size_t)bh*96*64);
        for (int u = tid; u < 768; u += 128) {
            ((uint4*)(abp + A_KHI))[u] = skh[u];
            ((uint4*)(abp + A_KLO))[u] = skl[u];
        }
        const uint4* svh = (const uint4*)(g_vimg_hi + (size_t)bh*64*128);
        const uint4* svl = (const uint4*)(g_vimg_lo + (size_t)bh*64*128);
        for (int u = tid; u < 1024; u += 128) {
            ((uint4*)(abp + A_VHI))[u] = svh[u];
            ((uint4*)(abp + A_VLO))[u] = svl[u];
        }
    }

    int par0 = 0, par1 = 0;
    for (int qt = 0; qt < ATT_QT; ++qt) {
        int qbase = (qg*ATT_QT + qt)*128;
        size_t qrow = (size_t)(b*NQ + qbase + tid)*INNER + h*DHEAD;
        // Q tile: thread t = row t, 128B per row hi + lo
        {
            const uint4* qh = (const uint4*)(g_qhi + qrow);
            const uint4* ql = (const uint4*)(g_qlo + qrow);
#pragma unroll
            for (int v = 0; v < 8; ++v) {
                uint32_t so = SMEM_SWIZZLE_128B((uint32_t)(tid*128 + v*16));
                *(uint4*)(abp + A_QHI + so) = qh[v];
                *(uint4*)(abp + A_QLO + so) = ql[v];
            }
        }
        __syncthreads();
        if (wid == 0 && elect_one_pred()) {
            FENCE_ASYNC();
            uint64_t dqh = MAKE_SMEM_DESC(ab + A_QHI);
            uint64_t dql = MAKE_SMEM_DESC(ab + A_QLO);
            uint64_t dkh = MAKE_SMEM_DESC(ab + A_KHI);
            uint64_t dkl = MAKE_SMEM_DESC(ab + A_KLO);
#pragma unroll
            for (int ks = 0; ks < 4; ++ks)
                mma_f16_ss(tmem, dqh + ks*2, dkh + ks*2, IDESC_S, ks > 0);
#pragma unroll
            for (int ks = 0; ks < 4; ++ks)
                mma_f16_ss(tmem, dqh + ks*2, dkl + ks*2, IDESC_S, true);
#pragma unroll
            for (int ks = 0; ks < 4; ++ks)
                mma_f16_ss(tmem, dql + ks*2, dkh + ks*2, IDESC_S, true);
            TCGEN05_COMMIT(sb + 8);
        }
        MBARRIER_WAIT_PARITY(sb + 8, par0); par0 ^= 1;
        TCGEN05_FENCE_AFTER();

        // read S row (96 cols), softmax
        float s[96];
#pragma unroll
        for (int cb = 0; cb < 3; ++cb) {
            uint32_t rr[32];
            TCGEN05_LD_32X32B_X32(rr, tmem + cb*32);
            TCGEN05_WAIT_LD();
#pragma unroll
            for (int i = 0; i < 32; ++i) s[cb*32 + i] = __uint_as_float(rr[i]);
        }
        TCGEN05_FENCE_BEFORE();
        int fg = g_fg[b*NQ + qbase + tid];
        float mx = -FLT_MAX;
#pragma unroll
        for (int j = 0; j < CTX; ++j) {
            float a = s[j] * 0.125f;
            bool valid = (j < 77) || ((j < 81) ? (fg != 0) : (fg == 0));
            a = valid ? a : -FLT_MAX;
            s[j] = a;
            mx = fmaxf(mx, a);
        }
        float sum = 0.f;
#pragma unroll
        for (int j = 0; j < CTX; ++j) {
            float e = (s[j] > -3.0e38f) ? __expf(s[j] - mx) : 0.f;
            s[j] = e;
            sum += e;
        }
        float inv = 1.f / sum;
#pragma unroll
        for (int j = CTX; j < 96; ++j) s[j] = 0.f;

        // store P hi/lo into blocked-atom SMEM image (row=tid, 128 cols, zeros >=85)
        {
            int r = tid;
#pragma unroll
            for (int g = 0; g < 16; ++g) {
                int c0 = g*8;
                uint32_t hv[4], lv[4];
#pragma unroll
                for (int pe = 0; pe < 4; ++pe) {
                    int c = c0 + 2*pe;
                    float f0 = (c < 96) ? s[c] : 0.f;
                    float f1 = (c+1 < 96) ? s[c+1] : 0.f;
                    ushort_t h0, l0, h1, l1;
                    bf16split(f0, h0, l0);
                    bf16split(f1, h1, l1);
                    hv[pe] = ((uint32_t)h1 << 16) | h0;
                    lv[pe] = ((uint32_t)l1 << 16) | l0;
                }
                uint32_t addr = (uint32_t)(((r >> 3) + (c0 >> 6)*16)*1024 + (r & 7)*128 + (c0 & 63)*2);
                uint32_t so = SMEM_SWIZZLE_128B(addr);
                *(uint4*)(abp + A_PHI + so) = make_uint4(hv[0], hv[1], hv[2], hv[3]);
                *(uint4*)(abp + A_PLO + so) = make_uint4(lv[0], lv[1], lv[2], lv[3]);
            }
        }
        __syncthreads();
        if (wid == 0 && elect_one_pred()) {
            FENCE_ASYNC();
            uint64_t dph = MAKE_SMEM_DESC(ab + A_PHI);
            uint64_t dpl = MAKE_SMEM_DESC(ab + A_PLO);
            uint64_t dvh = MAKE_SMEM_DESC(ab + A_VHI);
            uint64_t dvl = MAKE_SMEM_DESC(ab + A_VLO);
#pragma unroll
            for (int ks = 0; ks < 8; ++ks) {
                uint64_t aoff = (ks < 4) ? ks*2 : 1024 + (ks-4)*2;
                uint64_t boff = (ks < 4) ? ks*2 : 512 + (ks-4)*2;
                mma_f16_ss(tmem + 96, dph + aoff, dvh + boff, IDESC_O, ks > 0);
            }
#pragma unroll
            for (int ks = 0; ks < 8; ++ks) {
                uint64_t aoff = (ks < 4) ? ks*2 : 1024 + (ks-4)*2;
                uint64_t boff = (ks < 4) ? ks*2 : 512 + (ks-4)*2;
                mma_f16_ss(tmem + 96, dph + aoff, dvl + boff, IDESC_O, true);
            }
#pragma unroll
            for (int ks = 0; ks < 8; ++ks) {
                uint64_t aoff = (ks < 4) ? ks*2 : 1024 + (ks-4)*2;
                uint64_t boff = (ks < 4) ? ks*2 : 512 + (ks-4)*2;
                mma_f16_ss(tmem + 96, dpl + aoff, dvh + boff, IDESC_O, true);
            }
            TCGEN05_COMMIT(sb + 16);
        }
        MBARRIER_WAIT_PARITY(sb + 16, par1); par1 ^= 1;
        TCGEN05_FENCE_AFTER();

        // read O row (64 cols), normalize, write bf16 hi/lo
        size_t obase = (size_t)(b*NQ + qbase + tid)*INNER + h*DHEAD;
#pragma unroll
        for (int cb = 0; cb < 2; ++cb) {
            uint32_t rr[32];
            TCGEN05_LD_32X32B_X32(rr, tmem + 96 + cb*32);
            TCGEN05_WAIT_LD();
#pragma unroll
            for (int g = 0; g < 4; ++g) {
                uint32_t hv[4], lv[4];
#pragma unroll
                for (int pe = 0; pe < 4; ++pe) {
                    float f0 = __uint_as_float(rr[g*8 + 2*pe])     * inv;
                    float f1 = __uint_as_float(rr[g*8 + 2*pe + 1]) * inv;
                    ushort_t h0, l0, h1, l1;
                    bf16split(f0, h0, l0);
                    bf16split(f1, h1, l1);
                    hv[pe] = ((uint32_t)h1 << 16) | h0;
                    lv[pe] = ((uint32_t)l1 << 16) | l0;
                }
                *(uint4*)(g_ao_hi + obase + cb*32 + g*8) = make_uint4(hv[0], hv[1], hv[2], hv[3]);
                *(uint4*)(g_ao_lo + obase + cb*32 + g*8) = make_uint4(lv[0], lv[1], lv[2], lv[3]);
            }
        }
        TCGEN05_FENCE_BEFORE();
        __syncthreads();
    }
    if (wid == 0) TCGEN05_DEALLOC(tmem, 256);
#endif
}

// ---------------- launch ------------------------------------------------------
extern "C" void kernel_launch(void* const* d_in, const int* in_sizes, int n_in,
                              void* d_out, int out_size)
{
    (void)in_sizes; (void)n_in; (void)out_size;
    const float* x    = (const float*)d_in[0];
    const float* ctxp = (const float*)d_in[1];
    const float* Wq   = (const float*)d_in[2];
    const float* Wk   = (const float*)d_in[3];
    const float* Wv   = (const float*)d_in[4];
    const float* Wo   = (const float*)d_in[5];
    const float* bo   = (const float*)d_in[6];
    const int*   mask = (const int*)d_in[7];
    float* out = (float*)d_out;

    float *k, *v;
    __nv_bfloat16 *xhi, *xlo, *chi, *clo, *qhi, *qlo, *aohi, *aolo;
    __nv_bfloat16 *wqth, *wqtl, *wkth, *wktl, *wvth, *wvtl, *woth, *wotl;
    cudaGetSymbolAddress((void**)&k,    g_k);
    cudaGetSymbolAddress((void**)&v,    g_v);
    cudaGetSymbolAddress((void**)&xhi,  g_xhi);
    cudaGetSymbolAddress((void**)&xlo,  g_xlo);
    cudaGetSymbolAddress((void**)&chi,  g_chi);
    cudaGetSymbolAddress((void**)&clo,  g_clo);
    cudaGetSymbolAddress((void**)&qhi,  g_qhi);
    cudaGetSymbolAddress((void**)&qlo,  g_qlo);
    cudaGetSymbolAddress((void**)&aohi, g_ao_hi);
    cudaGetSymbolAddress((void**)&aolo, g_ao_lo);
    cudaGetSymbolAddress((void**)&wqth, g_wqt_hi);
    cudaGetSymbolAddress((void**)&wqtl, g_wqt_lo);
    cudaGetSymbolAddress((void**)&wkth, g_wkt_hi);
    cudaGetSymbolAddress((void**)&wktl, g_wkt_lo);
    cudaGetSymbolAddress((void**)&wvth, g_wvt_hi);
    cudaGetSymbolAddress((void**)&wvtl, g_wvt_lo);
    cudaGetSymbolAddress((void**)&woth, g_wot_hi);
    cudaGetSymbolAddress((void**)&wotl, g_wot_lo);

    cudaFuncSetAttribute(gemm_bf16x3, cudaFuncAttributeMaxDynamicSharedMemorySize, G_SMEM);
    cudaFuncSetAttribute(attn_tc, cudaFuncAttributeMaxDynamicSharedMemorySize, ATTN_SMEM);

    // 1. mask (exact integer stencil)
    mask_kernel<<<(BB*NQ + 255)/256, 256>>>(mask);

    // 2. weight transpose + split
    {
        dim3 blk(32, 8);
        wtrans_kernel<<<dim3(QD/32, INNER/32), blk>>>(Wq, wqth, wqtl, QD, INNER);
        wtrans_kernel<<<dim3(CD/32, INNER/32), blk>>>(Wk, wkth, wktl, CD, INNER);
        wtrans_kernel<<<dim3(CD/32, INNER/32), blk>>>(Wv, wvth, wvtl, CD, INNER);
        wtrans_kernel<<<dim3(INNER/32, QD/32), blk>>>(Wo, woth, wotl, INNER, QD);
    }

    // 3. activation splits
    {
        int n4 = BB*NQ*QD/4;
        split_kernel<<<(n4 + 255)/256, 256>>>(x, xhi, xlo, n4, n4);
        int n4t = MKV*CD/4, n4v = BB*CTX*CD/4;
        split_kernel<<<(n4t + 255)/256, 256>>>(ctxp, chi, clo, n4t, n4v);
    }

    // 4. K, V projections on tensor cores: [768,1024] x [1024,1280] -> fp32
    gemm_bf16x3<<<dim3(INNER/G_BN, MKV/G_BM), 256, G_SMEM>>>(
        chi, clo, wkth, wktl, nullptr, k, nullptr, nullptr, MKV, INNER, CD);
    gemm_bf16x3<<<dim3(INNER/G_BN, MKV/G_BM), 256, G_SMEM>>>(
        chi, clo, wvth, wvtl, nullptr, v, nullptr, nullptr, MKV, INNER, CD);

    // 5. Q projection -> bf16 hi/lo directly
    gemm_bf16x3<<<dim3(INNER/G_BN, (BB*NQ)/G_BM), 256, G_SMEM>>>(
        xhi, xlo, wqth, wqtl, nullptr, nullptr, qhi, qlo, BB*NQ, INNER, QD);

    // 6. bake K / V^T swizzled images
    kv_image_kernel<<<NBH, 128>>>();

    // 7. tensor-core masked attention
    attn_tc<<<dim3(NQ/(ATT_QT*128), NHEADS, BB), 128, ATTN_SMEM>>>();

    // 8. output projection + bias
    gemm_bf16x3<<<dim3(QD/G_BN, (BB*NQ)/G_BM), 256, G_SMEM>>>(
        aohi, aolo, woth, wotl, bo, out, nullptr, nullptr, BB*NQ, QD, INNER);
}